// round 1
// baseline (speedup 1.0000x reference)
#include <cuda_runtime.h>
#include <math.h>
#include <float.h>

#define NN    8192
#define DIM   512
#define TOPK  10
#define SCALE 0.04419417382415922f   // 512^-0.5 rounded to fp32

// 32 MB fp32 scratch for the two embeddings (static device alloc: allowed)
__device__ float g_e[2][NN * DIM];

// ---------------------------------------------------------------------------
// Kernel 1: E_z = X @ W_z^T + b_z   (z=0: Wh/bh, z=1: Wt/bt)
// Tile: BM=128, BN=64, BK=16, 256 threads, per-thread 8x4 (rows split 4+4)
// ---------------------------------------------------------------------------
__global__ __launch_bounds__(256) void embed_gemm(
    const float* __restrict__ X,
    const float* __restrict__ Wh, const float* __restrict__ bh,
    const float* __restrict__ Wt, const float* __restrict__ bt)
{
    const float* __restrict__ W  = blockIdx.z ? Wt : Wh;
    const float* __restrict__ bz = blockIdx.z ? bt : bh;
    float* E = g_e[blockIdx.z];

    __shared__ float As[16 * 132];   // [k][m], padded
    __shared__ float Bs[16 * 68];    // [k][n], padded

    const int tid = threadIdx.x;
    const int tx = tid & 15, ty = tid >> 4;
    const int brow = blockIdx.y * 128;
    const int bcol = blockIdx.x * 64;

    float acc[8][4];
    #pragma unroll
    for (int i = 0; i < 8; i++)
        #pragma unroll
        for (int j = 0; j < 4; j++) acc[i][j] = 0.f;

    for (int kt = 0; kt < DIM; kt += 16) {
        // A chunk: 128 rows x 16 k  (512 float4, 2 per thread), store transposed
        #pragma unroll
        for (int i = 0; i < 2; i++) {
            int lin = tid + i * 256;
            int r = lin >> 2, kq = (lin & 3) * 4;
            float4 v = *(const float4*)(X + (size_t)(brow + r) * DIM + kt + kq);
            As[(kq + 0) * 132 + r] = v.x; As[(kq + 1) * 132 + r] = v.y;
            As[(kq + 2) * 132 + r] = v.z; As[(kq + 3) * 132 + r] = v.w;
        }
        // B chunk: 64 rows x 16 k (256 float4, 1 per thread), store transposed
        {
            int r = tid >> 2, kq = (tid & 3) * 4;
            float4 v = *(const float4*)(W + (size_t)(bcol + r) * DIM + kt + kq);
            Bs[(kq + 0) * 68 + r] = v.x; Bs[(kq + 1) * 68 + r] = v.y;
            Bs[(kq + 2) * 68 + r] = v.z; Bs[(kq + 3) * 68 + r] = v.w;
        }
        __syncthreads();
        #pragma unroll
        for (int kk = 0; kk < 16; kk++) {
            float4 a0 = *(float4*)(As + kk * 132 + 4 * ty);
            float4 a1 = *(float4*)(As + kk * 132 + 64 + 4 * ty);
            float4 b  = *(float4*)(Bs + kk * 68 + 4 * tx);
            float av[8] = {a0.x, a0.y, a0.z, a0.w, a1.x, a1.y, a1.z, a1.w};
            float bw[4] = {b.x, b.y, b.z, b.w};
            #pragma unroll
            for (int i = 0; i < 8; i++)
                #pragma unroll
                for (int j = 0; j < 4; j++)
                    acc[i][j] = fmaf(av[i], bw[j], acc[i][j]);
        }
        __syncthreads();
    }
    float4 bb = *(const float4*)(bz + bcol + 4 * tx);
    #pragma unroll
    for (int i = 0; i < 8; i++) {
        int row = brow + ((i < 4) ? (4 * ty + i) : (64 + 4 * ty + (i - 4)));
        float4 o;
        o.x = acc[i][0] + bb.x; o.y = acc[i][1] + bb.y;
        o.z = acc[i][2] + bb.z; o.w = acc[i][3] + bb.w;
        *(float4*)(E + (size_t)row * DIM + bcol + 4 * tx) = o;
    }
}

// ---------------------------------------------------------------------------
// Kernel 2: fused logits GEMM + per-row top-10 + softmax + edge emit.
// One CTA per 64 rows (128 CTAs). e_h tile resident in smem (transposed),
// e_t streamed in 128-col x 16-k double-buffered chunks.
// ---------------------------------------------------------------------------
#define LDA 68
#define LDB 132
#define LDL 132
#define AH_FLOATS (DIM * LDA)            // 34816
#define BS_FLOATS (2 * 16 * LDB)         // 4224
#define LS_FLOATS (64 * LDL)             // 8448
#define SMEM_FLOATS (AH_FLOATS + BS_FLOATS + LS_FLOATS)   // 47488 -> 189952 B

__global__ __launch_bounds__(256) void logits_topk(float* __restrict__ out)
{
    extern __shared__ float sm[];
    float* Ah  = sm;                         // [k][m]  e_h tile, transposed
    float* Bsm = sm + AH_FLOATS;             // [2][16][n] e_t chunk, transposed
    float* Ls  = sm + AH_FLOATS + BS_FLOATS; // [64][128+] logits tile

    const float* __restrict__ eh = g_e[0];
    const float* __restrict__ et = g_e[1];

    const int tid = threadIdx.x;
    const int tx = tid & 15, ty = tid >> 4;
    const int brow = blockIdx.x * 64;

    // ---- phase 0: load e_h rows [64][512] -> Ah[k][m] ----
    #pragma unroll
    for (int i = 0; i < 32; i++) {
        int lin = tid + i * 256;
        int r = lin >> 7;
        int kq = (lin & 127) * 4;
        float4 v = *(const float4*)(eh + (size_t)(brow + r) * DIM + kq);
        Ah[(kq + 0) * LDA + r] = v.x; Ah[(kq + 1) * LDA + r] = v.y;
        Ah[(kq + 2) * LDA + r] = v.z; Ah[(kq + 3) * LDA + r] = v.w;
    }

    // per-thread partial top-10 (row = tid/4, column quarter = tid%4)
    float tv[TOPK]; int ti[TOPK];
    #pragma unroll
    for (int s = 0; s < TOPK; s++) { tv[s] = -FLT_MAX; ti[s] = 0; }
    const int qr = tid >> 2;
    const int qc = (tid & 3) * 32;

    // B loader indices (128 rows x 16 k -> 512 float4, 2 per thread)
    const int r0 = tid >> 2,        k0 = (tid & 3) * 4;
    const int r1 = (tid + 256) >> 2, k1 = ((tid + 256) & 3) * 4;

    __syncthreads();

    for (int ct = 0; ct < NN; ct += 128) {
        // prime k-chunk 0
        float4 p0 = *(const float4*)(et + (size_t)(ct + r0) * DIM + k0);
        float4 p1 = *(const float4*)(et + (size_t)(ct + r1) * DIM + k1);
        Bsm[(k0 + 0) * LDB + r0] = p0.x; Bsm[(k0 + 1) * LDB + r0] = p0.y;
        Bsm[(k0 + 2) * LDB + r0] = p0.z; Bsm[(k0 + 3) * LDB + r0] = p0.w;
        Bsm[(k1 + 0) * LDB + r1] = p1.x; Bsm[(k1 + 1) * LDB + r1] = p1.y;
        Bsm[(k1 + 2) * LDB + r1] = p1.z; Bsm[(k1 + 3) * LDB + r1] = p1.w;
        __syncthreads();

        float acc[4][8];
        #pragma unroll
        for (int i = 0; i < 4; i++)
            #pragma unroll
            for (int j = 0; j < 8; j++) acc[i][j] = 0.f;

        for (int kt = 0; kt < 32; kt++) {
            int cur = kt & 1;
            if (kt < 31) {
                p0 = *(const float4*)(et + (size_t)(ct + r0) * DIM + (kt + 1) * 16 + k0);
                p1 = *(const float4*)(et + (size_t)(ct + r1) * DIM + (kt + 1) * 16 + k1);
            }
            const float* Bc = Bsm + cur * 16 * LDB;
            #pragma unroll
            for (int kk = 0; kk < 16; kk++) {
                float4 a  = *(float4*)(Ah + (kt * 16 + kk) * LDA + 4 * ty);
                float4 b0 = *(float4*)(Bc + kk * LDB + 4 * tx);
                float4 b1 = *(float4*)(Bc + kk * LDB + 64 + 4 * tx);
                float av[4] = {a.x, a.y, a.z, a.w};
                float bv[8] = {b0.x, b0.y, b0.z, b0.w, b1.x, b1.y, b1.z, b1.w};
                #pragma unroll
                for (int i = 0; i < 4; i++)
                    #pragma unroll
                    for (int j = 0; j < 8; j++)
                        acc[i][j] = fmaf(av[i], bv[j], acc[i][j]);
            }
            if (kt < 31) {
                float* Bn = Bsm + (cur ^ 1) * 16 * LDB;
                Bn[(k0 + 0) * LDB + r0] = p0.x; Bn[(k0 + 1) * LDB + r0] = p0.y;
                Bn[(k0 + 2) * LDB + r0] = p0.z; Bn[(k0 + 3) * LDB + r0] = p0.w;
                Bn[(k1 + 0) * LDB + r1] = p1.x; Bn[(k1 + 1) * LDB + r1] = p1.y;
                Bn[(k1 + 2) * LDB + r1] = p1.z; Bn[(k1 + 3) * LDB + r1] = p1.w;
            }
            __syncthreads();
        }

        // dump tile to smem for top-k redistribution
        #pragma unroll
        for (int i = 0; i < 4; i++) {
            float4 o0 = {acc[i][0], acc[i][1], acc[i][2], acc[i][3]};
            float4 o1 = {acc[i][4], acc[i][5], acc[i][6], acc[i][7]};
            *(float4*)(Ls + (4 * ty + i) * LDL + 4 * tx) = o0;
            *(float4*)(Ls + (4 * ty + i) * LDL + 64 + 4 * tx) = o1;
        }
        __syncthreads();

        // scan: each thread scans 32 columns of its row, ascending (stable order)
        #pragma unroll 8
        for (int j = 0; j < 32; j++) {
            float v = Ls[qr * LDL + qc + j];
            if (v > tv[TOPK - 1]) {
                float cv = v; int ci = ct + qc + j;
                #pragma unroll
                for (int s = 0; s < TOPK; s++) {
                    if (cv > tv[s]) {
                        float tf = tv[s]; tv[s] = cv; cv = tf;
                        int tii = ti[s];  ti[s] = ci; ci = tii;
                    }
                }
            }
        }
        __syncthreads();
    }

    // ---- merge 4 partial lists per row, softmax, emit ----
    float* candv = Ls;                      // reuse logits tile
    int*   candi = (int*)(Ls + 64 * 40);
    #pragma unroll
    for (int s = 0; s < TOPK; s++) {
        candv[qr * 40 + (tid & 3) * TOPK + s] = tv[s];
        candi[qr * 40 + (tid & 3) * TOPK + s] = ti[s];
    }
    __syncthreads();

    if (tid < 64) {
        int r = tid;
        float wv[TOPK]; int wi[TOPK];
        #pragma unroll
        for (int s = 0; s < TOPK; s++) {
            float bvv = -FLT_MAX; int bii = 0x7fffffff; int bc = 0;
            for (int c = 0; c < 40; c++) {
                float v = candv[r * 40 + c];
                int  ii = candi[r * 40 + c];
                if (v > bvv || (v == bvv && ii < bii)) { bvv = v; bii = ii; bc = c; }
            }
            candv[r * 40 + bc] = -FLT_MAX;   // remove winner
            wv[s] = bvv; wi[s] = bii;
        }
        float pw[TOPK], psum = 0.f;
        #pragma unroll
        for (int s = 0; s < TOPK; s++) {
            pw[s] = __expf((wv[s] - wv[0]) * SCALE);
            psum += pw[s];
        }
        float inv = 1.0f / psum;
        int row = brow + r;
        #pragma unroll
        for (int s = 0; s < TOPK; s++) {
            out[(size_t)row * TOPK + s]                      = (float)row;   // src
            out[(size_t)NN * TOPK + (size_t)row * TOPK + s]  = (float)wi[s]; // dst
            out[(size_t)2 * NN * TOPK + (size_t)row * TOPK + s] = pw[s] * inv; // weight
        }
    }
}

// ---------------------------------------------------------------------------
extern "C" void kernel_launch(void* const* d_in, const int* in_sizes, int n_in,
                              void* d_out, int out_size)
{
    const float* X  = (const float*)d_in[0];
    const float* Wh = (const float*)d_in[1];
    const float* bh = (const float*)d_in[2];
    const float* Wt = (const float*)d_in[3];
    const float* bt = (const float*)d_in[4];
    float* out = (float*)d_out;

    cudaFuncSetAttribute(logits_topk, cudaFuncAttributeMaxDynamicSharedMemorySize,
                         SMEM_FLOATS * sizeof(float));

    embed_gemm<<<dim3(DIM / 64, NN / 128, 2), 256>>>(X, Wh, bh, Wt, bt);
    logits_topk<<<NN / 64, 256, SMEM_FLOATS * sizeof(float)>>>(out);
}

// round 5
// speedup vs baseline: 1.1655x; 1.1655x over previous
#include <cuda_runtime.h>
#include <math.h>
#include <float.h>

#define NN    8192
#define DIM   512
#define TOPK  10
#define SCALE 0.04419417382415922f   // 512^-0.5 rounded to fp32

typedef unsigned long long ull;

// 32 MB fp32 scratch for the two embeddings (static device alloc: allowed)
__device__ float g_e[2][NN * DIM];

// packed fp32x2 FMA (SASS FFMA2) — bit-exact IEEE fp32 per lane
#define FMA2(d, a, b) asm("fma.rn.f32x2 %0, %1, %2, %0;" : "+l"(d) : "l"(a), "l"(b))
#define PACK2(d, f)   asm("mov.b64 %0, {%1, %1};" : "=l"(d) : "f"(f))

// ---------------------------------------------------------------------------
// Kernel 1: E_z = X @ W_z^T + b_z   (z=0: Wh/bh, z=1: Wt/bt)  (unchanged)
// ---------------------------------------------------------------------------
__global__ __launch_bounds__(256) void embed_gemm(
    const float* __restrict__ X,
    const float* __restrict__ Wh, const float* __restrict__ bh,
    const float* __restrict__ Wt, const float* __restrict__ bt)
{
    const float* __restrict__ W  = blockIdx.z ? Wt : Wh;
    const float* __restrict__ bz = blockIdx.z ? bt : bh;
    float* E = g_e[blockIdx.z];

    __shared__ float As[16 * 132];
    __shared__ float Bs[16 * 68];

    const int tid = threadIdx.x;
    const int tx = tid & 15, ty = tid >> 4;
    const int brow = blockIdx.y * 128;
    const int bcol = blockIdx.x * 64;

    float acc[8][4];
    #pragma unroll
    for (int i = 0; i < 8; i++)
        #pragma unroll
        for (int j = 0; j < 4; j++) acc[i][j] = 0.f;

    for (int kt = 0; kt < DIM; kt += 16) {
        #pragma unroll
        for (int i = 0; i < 2; i++) {
            int lin = tid + i * 256;
            int r = lin >> 2, kq = (lin & 3) * 4;
            float4 v = *(const float4*)(X + (size_t)(brow + r) * DIM + kt + kq);
            As[(kq + 0) * 132 + r] = v.x; As[(kq + 1) * 132 + r] = v.y;
            As[(kq + 2) * 132 + r] = v.z; As[(kq + 3) * 132 + r] = v.w;
        }
        {
            int r = tid >> 2, kq = (tid & 3) * 4;
            float4 v = *(const float4*)(W + (size_t)(bcol + r) * DIM + kt + kq);
            Bs[(kq + 0) * 68 + r] = v.x; Bs[(kq + 1) * 68 + r] = v.y;
            Bs[(kq + 2) * 68 + r] = v.z; Bs[(kq + 3) * 68 + r] = v.w;
        }
        __syncthreads();
        #pragma unroll
        for (int kk = 0; kk < 16; kk++) {
            float4 a0 = *(float4*)(As + kk * 132 + 4 * ty);
            float4 a1 = *(float4*)(As + kk * 132 + 64 + 4 * ty);
            float4 b  = *(float4*)(Bs + kk * 68 + 4 * tx);
            float av[8] = {a0.x, a0.y, a0.z, a0.w, a1.x, a1.y, a1.z, a1.w};
            float bw[4] = {b.x, b.y, b.z, b.w};
            #pragma unroll
            for (int i = 0; i < 8; i++)
                #pragma unroll
                for (int j = 0; j < 4; j++)
                    acc[i][j] = fmaf(av[i], bw[j], acc[i][j]);
        }
        __syncthreads();
    }
    float4 bb = *(const float4*)(bz + bcol + 4 * tx);
    #pragma unroll
    for (int i = 0; i < 8; i++) {
        int row = brow + ((i < 4) ? (4 * ty + i) : (64 + 4 * ty + (i - 4)));
        float4 o;
        o.x = acc[i][0] + bb.x; o.y = acc[i][1] + bb.y;
        o.z = acc[i][2] + bb.z; o.w = acc[i][3] + bb.w;
        *(float4*)(E + (size_t)row * DIM + bcol + 4 * tx) = o;
    }
}

// ---------------------------------------------------------------------------
// Kernel 2: fused logits GEMM (packed f32x2) + per-row top-10 + softmax.
// CTA = 64 rows x all 8192 cols, streamed in 256-col tiles.
// Thread tile 8x8: rows 8*ty..8*ty+7 (broadcast A), cols {4*tx..}+{128+4*tx..}
// ---------------------------------------------------------------------------
#define LDA   68
#define LDB2  260
#define LDL2  268
#define AH_FLOATS (DIM * LDA)           // 34816
#define LS_FLOATS (64 * LDL2)           // 17152
#define BUF_STRIDE (16 * LDB2)          // 4160  (2 bufs alias low part of Ls)
#define SMEM_FLOATS (AH_FLOATS + LS_FLOATS)   // 51968 -> 207872 B

__global__ __launch_bounds__(256) void logits_topk(float* __restrict__ out)
{
    extern __shared__ float sm[];
    float* Ah  = sm;                    // [k][row]  e_h tile, transposed
    float* Ls  = sm + AH_FLOATS;        // [64][268] logits tile / merge scratch
    float* Bsm = Ls;                    // [2][16][260]  aliases Ls (disjoint lifetime)

    const float* __restrict__ eh = g_e[0];
    const float* __restrict__ et = g_e[1];

    const int tid = threadIdx.x;
    const int tx = tid & 31, ty = tid >> 5;
    const int brow = blockIdx.x * 64;

    // ---- phase 0: load e_h rows [64][512] -> Ah[k][row] ----
    #pragma unroll
    for (int i = 0; i < 32; i++) {
        int lin = tid + i * 256;
        int r = lin >> 7;
        int kq = (lin & 127) * 4;
        float4 v = *(const float4*)(eh + (size_t)(brow + r) * DIM + kq);
        Ah[(kq + 0) * LDA + r] = v.x; Ah[(kq + 1) * LDA + r] = v.y;
        Ah[(kq + 2) * LDA + r] = v.z; Ah[(kq + 3) * LDA + r] = v.w;
    }

    // per-thread partial top-10 (row = tid/4, col range = (tid%3)*64)
    float tv[TOPK]; int ti[TOPK];
    #pragma unroll
    for (int s = 0; s < TOPK; s++) { tv[s] = -FLT_MAX; ti[s] = 0; }
    const int qr = tid >> 2;
    const int qc = (tid & 3) * 64;

    // B loader: 256 et-rows x 16 k per chunk; 4 float4 per thread
    const int lr = tid >> 2;            // base et-row within tile
    const int lk = (tid & 3) * 4;       // k offset

    __syncthreads();

    for (int ct = 0; ct < NN; ct += 256) {
        // prime k-chunk 0 into buf 0
        float4 p[4];
        #pragma unroll
        for (int i = 0; i < 4; i++)
            p[i] = *(const float4*)(et + (size_t)(ct + lr + 64 * i) * DIM + lk);
        #pragma unroll
        for (int i = 0; i < 4; i++) {
            float* Bn = Bsm;
            int r = lr + 64 * i;
            Bn[(lk + 0) * LDB2 + r] = p[i].x; Bn[(lk + 1) * LDB2 + r] = p[i].y;
            Bn[(lk + 2) * LDB2 + r] = p[i].z; Bn[(lk + 3) * LDB2 + r] = p[i].w;
        }
        __syncthreads();

        ull acc[8][4];
        #pragma unroll
        for (int i = 0; i < 8; i++)
            #pragma unroll
            for (int j = 0; j < 4; j++) acc[i][j] = 0ull;

        #pragma unroll 1
        for (int kt = 0; kt < 32; kt++) {
            const float* Bc = Bsm + (kt & 1) * BUF_STRIDE;
            float* Bn = Bsm + ((kt & 1) ^ 1) * BUF_STRIDE;
            if (kt < 31) {
                #pragma unroll
                for (int i = 0; i < 4; i++)
                    p[i] = *(const float4*)(et + (size_t)(ct + lr + 64 * i) * DIM
                                            + (kt + 1) * 16 + lk);
            }
            #pragma unroll
            for (int kk = 0; kk < 16; kk++) {
                float4 a0 = *(const float4*)(Ah + (kt * 16 + kk) * LDA + 8 * ty);
                float4 a1 = *(const float4*)(Ah + (kt * 16 + kk) * LDA + 8 * ty + 4);
                ulonglong2 b0 = *(const ulonglong2*)(Bc + kk * LDB2 + 4 * tx);
                ulonglong2 b1 = *(const ulonglong2*)(Bc + kk * LDB2 + 128 + 4 * tx);
                ull ap[8];
                PACK2(ap[0], a0.x); PACK2(ap[1], a0.y);
                PACK2(ap[2], a0.z); PACK2(ap[3], a0.w);
                PACK2(ap[4], a1.x); PACK2(ap[5], a1.y);
                PACK2(ap[6], a1.z); PACK2(ap[7], a1.w);
                #pragma unroll
                for (int i = 0; i < 8; i++) {
                    FMA2(acc[i][0], ap[i], b0.x);
                    FMA2(acc[i][1], ap[i], b0.y);
                    FMA2(acc[i][2], ap[i], b1.x);
                    FMA2(acc[i][3], ap[i], b1.y);
                }
            }
            if (kt < 31) {
                #pragma unroll
                for (int i = 0; i < 4; i++) {
                    int r = lr + 64 * i;
                    Bn[(lk + 0) * LDB2 + r] = p[i].x; Bn[(lk + 1) * LDB2 + r] = p[i].y;
                    Bn[(lk + 2) * LDB2 + r] = p[i].z; Bn[(lk + 3) * LDB2 + r] = p[i].w;
                }
            }
            __syncthreads();
        }

        // dump tile to smem (packed pairs stored verbatim = exact fp32 values)
        #pragma unroll
        for (int i = 0; i < 8; i++) {
            ulonglong2 o0; o0.x = acc[i][0]; o0.y = acc[i][1];
            ulonglong2 o1; o1.x = acc[i][2]; o1.y = acc[i][3];
            *(ulonglong2*)(Ls + (8 * ty + i) * LDL2 + 4 * tx) = o0;
            *(ulonglong2*)(Ls + (8 * ty + i) * LDL2 + 128 + 4 * tx) = o1;
        }
        __syncthreads();

        // scan: each thread scans 64 cols of its row, ascending (stable order)
        {
            const float* Lr = Ls + qr * LDL2 + qc;
            #pragma unroll 4
            for (int j = 0; j < 64; j++) {
                float v = Lr[j];
                if (v > tv[TOPK - 1]) {
                    float cv = v; int ci = ct + qc + j;
                    #pragma unroll
                    for (int s = 0; s < TOPK; s++) {
                        if (cv > tv[s]) {
                            float tf = tv[s]; tv[s] = cv; cv = tf;
                            int tii = ti[s];  ti[s] = ci; ci = tii;
                        }
                    }
                }
            }
        }
        __syncthreads();
    }

    // ---- merge 4 partial lists per row, softmax, emit ----
    float* candv = Ls;
    int*   candi = (int*)(Ls + 64 * 40);
    #pragma unroll
    for (int s = 0; s < TOPK; s++) {
        candv[qr * 40 + (tid & 3) * TOPK + s] = tv[s];
        candi[qr * 40 + (tid & 3) * TOPK + s] = ti[s];
    }
    __syncthreads();

    if (tid < 64) {
        int r = tid;
        float wv[TOPK]; int wi[TOPK];
        #pragma unroll
        for (int s = 0; s < TOPK; s++) {
            float bvv = -FLT_MAX; int bii = 0x7fffffff; int bc = 0;
            for (int c = 0; c < 40; c++) {
                float v = candv[r * 40 + c];
                int  ii = candi[r * 40 + c];
                if (v > bvv || (v == bvv && ii < bii)) { bvv = v; bii = ii; bc = c; }
            }
            candv[r * 40 + bc] = -FLT_MAX;
            wv[s] = bvv; wi[s] = bii;
        }
        float pw[TOPK], psum = 0.f;
        #pragma unroll
        for (int s = 0; s < TOPK; s++) {
            pw[s] = __expf((wv[s] - wv[0]) * SCALE);
            psum += pw[s];
        }
        float inv = 1.0f / psum;
        int row = brow + r;
        #pragma unroll
        for (int s = 0; s < TOPK; s++) {
            out[(size_t)row * TOPK + s]                         = (float)row;
            out[(size_t)NN * TOPK + (size_t)row * TOPK + s]     = (float)wi[s];
            out[(size_t)2 * NN * TOPK + (size_t)row * TOPK + s] = pw[s] * inv;
        }
    }
}

// ---------------------------------------------------------------------------
extern "C" void kernel_launch(void* const* d_in, const int* in_sizes, int n_in,
                              void* d_out, int out_size)
{
    const float* X  = (const float*)d_in[0];
    const float* Wh = (const float*)d_in[1];
    const float* bh = (const float*)d_in[2];
    const float* Wt = (const float*)d_in[3];
    const float* bt = (const float*)d_in[4];
    float* out = (float*)d_out;

    cudaFuncSetAttribute(logits_topk, cudaFuncAttributeMaxDynamicSharedMemorySize,
                         SMEM_FLOATS * sizeof(float));

    embed_gemm<<<dim3(DIM / 64, NN / 128, 2), 256>>>(X, Wh, bh, Wt, bt);
    logits_topk<<<NN / 64, 256, SMEM_FLOATS * sizeof(float)>>>(out);
}